// round 1
// baseline (speedup 1.0000x reference)
#include <cuda_runtime.h>
#include <cuda_bf16.h>

// DifferentiableHMM_Centered — GB300 sm_103a
//
// Reduction of the reference:
//   states = straight-through one-hot of argmax over (log_em + gumbel)  (softmax is
//   monotone; /TAU drops out of argmax). Non-argmax entries of states are EXACTLY 0
//   in fp32; the argmax entry is 1 within ~1 ulp.
//   => norm_copy[s,j] = all_means[argmax]
//   => diff*diff summed over 3 states per (edge, bin) = 2 * (argmax_row != argmax_col)
//   => smooth_loss = 0.1 * 2 * mismatch_count / (E * Bc * 3)
//
// Pipeline (graph-capturable, allocation-free):
//   setup_kernel (1 thread): exp/log of the 3 stds hoisted out of the hot loop
//   state_kernel: per-(s,j) argmax -> norm_copy (f32) + state byte (scratch)
//   edge_kernel : byte-mismatch count over edges (u64 + __vcmpne4), block-reduced
//   finalize    : scalar loss

#define HALF_LOG_2PI 0.9189385332046727f
#define MAX_SB (2048u * 3000u)

__device__ unsigned char g_state[MAX_SB];
__device__ unsigned int  g_count;
__device__ float         g_params[8]; // m0, m2, inv0, inv1, inv2, c0, c1, c2

__global__ void setup_kernel(const float* __restrict__ state_means,
                             const float* __restrict__ log_stds) {
    float s0 = expf(log_stds[0]) + 1e-6f;
    float s1 = expf(log_stds[1]) + 1e-6f;
    float s2 = expf(log_stds[2]) + 1e-6f;
    g_params[0] = state_means[0];
    g_params[1] = state_means[1];
    g_params[2] = 1.0f / s0;
    g_params[3] = 1.0f / s1;
    g_params[4] = 1.0f / s2;
    g_params[5] = -logf(s0) - HALF_LOG_2PI;
    g_params[6] = -logf(s1) - HALF_LOG_2PI;
    g_params[7] = -logf(s2) - HALF_LOG_2PI;
    g_count = 0u;
}

__global__ void state_kernel(const float* __restrict__ x,
                             const int*   __restrict__ bin_idx,
                             const float* __restrict__ gumbel,
                             float*       __restrict__ out,
                             int B, int Bc) {
    int j = blockIdx.x * blockDim.x + threadIdx.x;
    if (j >= Bc) return;
    int s = blockIdx.y;

    float m0 = g_params[0], m2 = g_params[1];
    float i0 = g_params[2], i1 = g_params[3], i2 = g_params[4];
    float c0 = g_params[5], c1 = g_params[6], c2 = g_params[7];

    int src = __ldg(bin_idx + j);
    size_t xi = (size_t)s * (size_t)B + (size_t)src;
    float xv = __ldg(x + xi);
    const float* g = gumbel + xi * 3u;
    float g0 = __ldg(g + 0), g1 = __ldg(g + 1), g2 = __ldg(g + 2);

    float z0 = (xv - m0) * i0;
    float z1 = xv * i1;                 // mean of middle state is 0
    float z2 = (xv - m2) * i2;
    float l0 = fmaf(-0.5f * z0, z0, c0) + g0;
    float l1 = fmaf(-0.5f * z1, z1, c1) + g1;
    float l2 = fmaf(-0.5f * z2, z2, c2) + g2;

    // first-max wins (matches jnp.argmax tie rule)
    int k = 0; float best = l0; float nv = m0;
    if (l1 > best) { best = l1; k = 1; nv = 0.0f; }
    if (l2 > best) {            k = 2; nv = m2;  }

    size_t oi = (size_t)s * (size_t)Bc + (size_t)j;
    out[oi] = nv;
    g_state[oi] = (unsigned char)k;
}

__global__ void edge_kernel(const int* __restrict__ edge_index,
                            int E, int Bc, int edges_per_block) {
    __shared__ unsigned int sred[256];
    unsigned int local = 0;
    int e0 = blockIdx.x * edges_per_block;
    int e1 = min(e0 + edges_per_block, E);
    int words = Bc >> 3;
    bool aligned = ((Bc & 7) == 0);

    for (int e = e0; e < e1; ++e) {
        int r = edge_index[e];
        int c = edge_index[E + e];
        if (r == c) continue;
        const unsigned char* pa = g_state + (size_t)r * (size_t)Bc;
        const unsigned char* pb = g_state + (size_t)c * (size_t)Bc;
        if (aligned) {
            const unsigned long long* a = (const unsigned long long*)pa;
            const unsigned long long* b = (const unsigned long long*)pb;
            for (int w = threadIdx.x; w < words; w += blockDim.x) {
                unsigned long long va = __ldg(a + w);
                unsigned long long vb = __ldg(b + w);
                if (va != vb) {
                    unsigned int d1 = __vcmpne4((unsigned int)(va & 0xffffffffull),
                                                (unsigned int)(vb & 0xffffffffull));
                    unsigned int d2 = __vcmpne4((unsigned int)(va >> 32),
                                                (unsigned int)(vb >> 32));
                    local += (unsigned int)(__popc(d1) + __popc(d2)) >> 3;
                }
            }
        } else {
            for (int q = threadIdx.x; q < Bc; q += blockDim.x)
                local += (pa[q] != pb[q]) ? 1u : 0u;
        }
    }

    sred[threadIdx.x] = local;
    __syncthreads();
    for (int off = blockDim.x >> 1; off > 0; off >>= 1) {
        if (threadIdx.x < (unsigned)off) sred[threadIdx.x] += sred[threadIdx.x + off];
        __syncthreads();
    }
    if (threadIdx.x == 0 && sred[0]) atomicAdd(&g_count, sred[0]);
}

__global__ void finalize_kernel(float* __restrict__ loss_out, long long denom) {
    double v = 0.2 * (double)g_count / (double)denom;  // LAMBDA * 2 * count / denom
    loss_out[0] = (float)v;
}

extern "C" void kernel_launch(void* const* d_in, const int* in_sizes, int n_in,
                              void* d_out, int out_size) {
    const float* x           = (const float*)d_in[0];
    const int*   bin_idx     = (const int*)  d_in[1];
    const int*   edge_index  = (const int*)  d_in[2];
    const float* gumbel      = (const float*)d_in[3];
    const float* state_means = (const float*)d_in[4];
    const float* log_stds    = (const float*)d_in[5];
    float* out = (float*)d_out;

    int Bc = in_sizes[1];            // covered bins (output columns)
    int E  = in_sizes[2] / 2;        // edges
    int B  = Bc;                     // bin ranges cover all bins => B == Bc
    int S  = in_sizes[0] / B;        // spots

    setup_kernel<<<1, 1>>>(state_means, log_stds);

    dim3 gridA((Bc + 255) / 256, S);
    state_kernel<<<gridA, 256>>>(x, bin_idx, gumbel, out, B, Bc);

    const int EPB = 8;
    int gridB = (E + EPB - 1) / EPB;
    edge_kernel<<<gridB, 256>>>(edge_index, E, Bc, EPB);

    long long denom = (long long)E * (long long)Bc * 3ll;
    finalize_kernel<<<1, 1>>>(out + ((size_t)out_size - 1), denom);
}

// round 2
// speedup vs baseline: 1.5251x; 1.5251x over previous
#include <cuda_runtime.h>
#include <cuda_bf16.h>

// DifferentiableHMM_Centered — GB300 sm_103a, R2
//
// Math reduction (see R1): straight-through gumbel-softmax argmax collapses to
//   norm_copy[s,j] = all_means[argmax_k(log_em_k + gumbel_k)]
//   smooth_loss    = 0.1 * 2 * (#(state[row] != state[col]) over edges×bins) / (E*Bc*3)
//
// R2: 2 kernels total (setup fused into state_kernel per-block; finalize fused
// into edge_kernel via last-block ticket). States packed 2 bits each -> edge
// kernel reads 18.9 MB from L2 instead of 73.7 MB. state_kernel float4 paths.

#define HALF_LOG_2PI 0.9189385332046727f

// 2048 rows x up to 128 u64 words (zero-initialized at module load; padding
// words are never written and stay 0 -> contribute 0 mismatches)
__device__ unsigned long long g_state[2048 * 128];
__device__ unsigned int g_count;
__device__ unsigned int g_done;

__device__ __forceinline__ void classify(float xv, float g0, float g1, float g2,
                                         const float* __restrict__ p,
                                         int& k, float& nv) {
    float z0 = (xv - p[0]) * p[2];
    float z1 = xv * p[3];              // middle state mean == 0
    float z2 = (xv - p[1]) * p[4];
    float l0 = fmaf(-0.5f * z0, z0, p[5]) + g0;
    float l1 = fmaf(-0.5f * z1, z1, p[6]) + g1;
    float l2 = fmaf(-0.5f * z2, z2, p[7]) + g2;
    k = 0; float best = l0; nv = p[0];
    if (l1 > best) { best = l1; k = 1; nv = 0.0f; }
    if (l2 > best) {            k = 2; nv = p[1]; }
}

__global__ void state_kernel(const float* __restrict__ x,
                             const int*   __restrict__ bin_idx,
                             const float* __restrict__ gumbel,
                             const float* __restrict__ state_means,
                             const float* __restrict__ log_stds,
                             float*       __restrict__ out,
                             int B, int Bc, int stride_bytes) {
    __shared__ float p[8];
    if (threadIdx.x == 0) {
        float s0 = expf(log_stds[0]) + 1e-6f;
        float s1 = expf(log_stds[1]) + 1e-6f;
        float s2 = expf(log_stds[2]) + 1e-6f;
        p[0] = state_means[0];
        p[1] = state_means[1];
        p[2] = 1.0f / s0;  p[3] = 1.0f / s1;  p[4] = 1.0f / s2;
        p[5] = -logf(s0) - HALF_LOG_2PI;
        p[6] = -logf(s1) - HALF_LOG_2PI;
        p[7] = -logf(s2) - HALF_LOG_2PI;
        if (blockIdx.x == 0 && blockIdx.y == 0) { g_count = 0u; g_done = 0u; }
    }
    __syncthreads();

    int groups = (Bc + 3) >> 2;
    int jt = blockIdx.x * blockDim.x + threadIdx.x;
    if (jt >= groups) return;
    int s  = blockIdx.y;
    int j0 = jt << 2;

    unsigned int pack = 0;
    float nv0 = 0.f, nv1 = 0.f, nv2 = 0.f, nv3 = 0.f;
    bool full = (j0 + 3 < Bc);
    bool fast = false;
    int src0 = __ldg(bin_idx + j0);
    size_t base = (size_t)s * (size_t)B + (size_t)src0;

    if (full) {
        int src1 = __ldg(bin_idx + j0 + 1);
        int src2 = __ldg(bin_idx + j0 + 2);
        int src3 = __ldg(bin_idx + j0 + 3);
        fast = (src1 == src0 + 1) && (src2 == src0 + 2) && (src3 == src0 + 3) &&
               ((base & 3) == 0);
        if (fast) {
            float4 xv = __ldg((const float4*)(x + base));
            const float4* g4 = (const float4*)(gumbel + base * 3u);
            float4 ga = __ldg(g4), gb = __ldg(g4 + 1), gc = __ldg(g4 + 2);
            int k;
            classify(xv.x, ga.x, ga.y, ga.z, p, k, nv0); pack  = (unsigned)k;
            classify(xv.y, ga.w, gb.x, gb.y, p, k, nv1); pack |= (unsigned)k << 2;
            classify(xv.z, gb.z, gb.w, gc.x, p, k, nv2); pack |= (unsigned)k << 4;
            classify(xv.w, gc.y, gc.z, gc.w, p, k, nv3); pack |= (unsigned)k << 6;
        }
    }
    if (!fast) {
        float nv[4] = {0.f, 0.f, 0.f, 0.f};
        for (int u = 0; u < 4; ++u) {
            int j = j0 + u;
            if (j >= Bc) break;
            int src = __ldg(bin_idx + j);
            size_t xi = (size_t)s * (size_t)B + (size_t)src;
            float xv = __ldg(x + xi);
            const float* g = gumbel + xi * 3u;
            int k;
            classify(xv, __ldg(g), __ldg(g + 1), __ldg(g + 2), p, k, nv[u]);
            pack |= (unsigned)k << (2 * u);
        }
        nv0 = nv[0]; nv1 = nv[1]; nv2 = nv[2]; nv3 = nv[3];
    }

    size_t oi = (size_t)s * (size_t)Bc + (size_t)j0;
    if (full && ((oi & 3) == 0)) {
        *(float4*)(out + oi) = make_float4(nv0, nv1, nv2, nv3);
    } else {
        if (j0 + 0 < Bc) out[oi + 0] = nv0;
        if (j0 + 1 < Bc) out[oi + 1] = nv1;
        if (j0 + 2 < Bc) out[oi + 2] = nv2;
        if (j0 + 3 < Bc) out[oi + 3] = nv3;
    }
    ((unsigned char*)g_state)[(size_t)s * (size_t)stride_bytes + (size_t)jt] =
        (unsigned char)pack;
}

__global__ void edge_kernel(const int* __restrict__ edge_index,
                            int E, int stride_words,
                            float* __restrict__ loss_out, long long denom) {
    int warp = threadIdx.x >> 5;
    int lane = threadIdx.x & 31;
    int e = blockIdx.x * (blockDim.x >> 5) + warp;

    unsigned int cnt = 0;
    if (e < E) {
        int r = __ldg(edge_index + e);
        int c = __ldg(edge_index + E + e);
        if (r != c) {
            const unsigned long long* a = g_state + (size_t)r * (size_t)stride_words;
            const unsigned long long* b = g_state + (size_t)c * (size_t)stride_words;
            for (int w = lane; w < stride_words; w += 32) {
                unsigned long long d = __ldg(a + w) ^ __ldg(b + w);
                d = (d | (d >> 1)) & 0x5555555555555555ull;
                cnt += (unsigned)__popcll(d);
            }
        }
    }
    cnt = __reduce_add_sync(0xffffffffu, cnt);

    __shared__ unsigned int sred[32];
    if (lane == 0) sred[warp] = cnt;
    __syncthreads();
    if (threadIdx.x == 0) {
        unsigned int tot = 0;
        int nw = blockDim.x >> 5;
        for (int i = 0; i < nw; ++i) tot += sred[i];
        if (tot) atomicAdd(&g_count, tot);
        __threadfence();
        unsigned int ticket = atomicAdd(&g_done, 1u);
        if (ticket == gridDim.x - 1) {
            unsigned int total = atomicAdd(&g_count, 0u);  // ordered read
            loss_out[0] = (float)(0.2 * (double)total / (double)denom);
            g_done = 0u;  // reset for next graph replay
        }
    }
}

extern "C" void kernel_launch(void* const* d_in, const int* in_sizes, int n_in,
                              void* d_out, int out_size) {
    const float* x           = (const float*)d_in[0];
    const int*   bin_idx     = (const int*)  d_in[1];
    const int*   edge_index  = (const int*)  d_in[2];
    const float* gumbel      = (const float*)d_in[3];
    const float* state_means = (const float*)d_in[4];
    const float* log_stds    = (const float*)d_in[5];
    float* out = (float*)d_out;

    int Bc = in_sizes[1];          // covered bins (output columns)
    int E  = in_sizes[2] / 2;      // edges
    int B  = Bc;                   // ranges cover all bins => B == Bc
    int S  = in_sizes[0] / B;      // spots

    int groups       = (Bc + 3) / 4;          // state bytes per row
    int stride_words = (groups + 7) / 8;      // u64 words per packed row
    int stride_bytes = stride_words * 8;

    dim3 gridA((groups + 255) / 256, S);
    state_kernel<<<gridA, 256>>>(x, bin_idx, gumbel, state_means, log_stds,
                                 out, B, Bc, stride_bytes);

    const int WARPS_PER_BLOCK = 8;
    int gridB = (E + WARPS_PER_BLOCK - 1) / WARPS_PER_BLOCK;
    long long denom = (long long)E * (long long)Bc * 3ll;
    edge_kernel<<<gridB, WARPS_PER_BLOCK * 32>>>(
        edge_index, E, stride_words, out + ((size_t)out_size - 1), denom);
}